// round 1
// baseline (speedup 1.0000x reference)
#include <cuda_runtime.h>
#include <cstdint>
#include <cstddef>

#define B_ 64
#define S_ 2048
#define H_ 512
#define NEG_INF_V (-1e10f)

// ---------------- scratch (no allocations allowed) ----------------
__device__ float g_q[B_ * H_];        // query projection  [B,H]
__device__ float g_energy[B_ * S_];   // masked energies   [B,S]
__device__ float g_mx[B_];            // per-b max
__device__ float g_invden[B_];        // per-b 1/sum(exp)

// ---------------- f32x2 helpers (FFMA2: full-rate fp32 on sm_103a) ----------
__device__ __forceinline__ unsigned long long pack_dup(float x) {
    unsigned long long r;
    asm("mov.b64 %0, {%1, %1};" : "=l"(r) : "f"(x));
    return r;
}
__device__ __forceinline__ unsigned long long fma2(unsigned long long a,
                                                   unsigned long long b,
                                                   unsigned long long c) {
    unsigned long long d;
    asm("fma.rn.f32x2 %0, %1, %2, %3;" : "=l"(d) : "l"(a), "l"(b), "l"(c));
    return d;
}
__device__ __forceinline__ float2 unpack2(unsigned long long v) {
    float2 f;
    asm("mov.b64 {%0, %1}, %2;" : "=f"(f.x), "=f"(f.y) : "l"(v));
    return f;
}

// Accurate-enough fast tanh: 1 - 2/(e^{2x}+1). Handles +-inf limits correctly.
__device__ __forceinline__ float tanh_fast(float x) {
    float e = __expf(2.0f * x);
    return 1.0f - __fdividef(2.0f, e + 1.0f);
}

// ---------------- K1: q[b] = dec[b] @ W2 ----------------
__global__ __launch_bounds__(512) void qproj_kernel(const float* __restrict__ dec,
                                                    const float* __restrict__ W2) {
    int b = blockIdx.x;
    __shared__ float xs[H_];
    xs[threadIdx.x] = dec[b * H_ + threadIdx.x];
    __syncthreads();
    float acc = 0.f;
#pragma unroll 8
    for (int h = 0; h < H_; ++h)
        acc += xs[h] * W2[(size_t)h * H_ + threadIdx.x];
    g_q[b * H_ + threadIdx.x] = acc;
}

// ---------------- K2: fused energy GEMM ----------------
// CTA tile: 64 rows (one batch) x full H, processed in 4 N-chunks of 128.
// 256 threads, 16x16 layout, each thread owns a 4x8 micro-tile (as 4x4 f32x2).
__global__ __launch_bounds__(256) void energy_kernel(const float* __restrict__ enc,
                                                     const float* __restrict__ W1,
                                                     const float* __restrict__ Vv,
                                                     const int* __restrict__ lens) {
    constexpr int TM = 64, TN = 128, TK = 16;
    __shared__ float As[TK][TM + 4];   // transposed A tile: [k][row]
    __shared__ float Bs[TK][TN + 4];   // B tile: [k][n]
    __shared__ float qs[H_];
    __shared__ float Vs[H_];
    __shared__ float es[TM];

    const int b    = blockIdx.x >> 5;       // S_/TM = 32 tiles per batch
    const int tile = blockIdx.x & 31;
    const int row0 = tile * TM;
    const int tid  = threadIdx.x;
    const int tx   = tid & 15;
    const int ty   = tid >> 4;

    qs[tid]       = g_q[b * H_ + tid];
    qs[tid + 256] = g_q[b * H_ + tid + 256];
    Vs[tid]       = Vv[tid];
    Vs[tid + 256] = Vv[tid + 256];
    if (tid < TM) es[tid] = 0.f;
    __syncthreads();

    const float* Abase = enc + ((size_t)b * S_ + row0) * H_;
    const int arow = tid >> 2;          // 0..63
    const int aq   = (tid & 3) * 4;     // 0,4,8,12
    const int brow = tid >> 4;          // 0..15
    const int bc   = (tid & 15) * 8;    // 0..120

    for (int nc = 0; nc < 4; ++nc) {
        const int n0 = nc * TN;
        unsigned long long acc[4][4];
#pragma unroll
        for (int i = 0; i < 4; ++i)
#pragma unroll
            for (int j = 0; j < 4; ++j) acc[i][j] = 0ULL;

        for (int kt = 0; kt < H_; kt += TK) {
            // load A tile (transpose into [k][row])
            float4 av = *(const float4*)(Abase + (size_t)arow * H_ + kt + aq);
            As[aq + 0][arow] = av.x;
            As[aq + 1][arow] = av.y;
            As[aq + 2][arow] = av.z;
            As[aq + 3][arow] = av.w;
            // load B tile
            const float* wrow = W1 + (size_t)(kt + brow) * H_ + n0 + bc;
            *(float4*)&Bs[brow][bc]     = *(const float4*)wrow;
            *(float4*)&Bs[brow][bc + 4] = *(const float4*)(wrow + 4);
            __syncthreads();

#pragma unroll
            for (int k = 0; k < TK; ++k) {
                float4 afr = *(const float4*)&As[k][ty * 4];
                ulonglong2 b01 = *(const ulonglong2*)&Bs[k][tx * 8];
                ulonglong2 b23 = *(const ulonglong2*)&Bs[k][tx * 8 + 4];
                unsigned long long a0 = pack_dup(afr.x);
                unsigned long long a1 = pack_dup(afr.y);
                unsigned long long a2 = pack_dup(afr.z);
                unsigned long long a3 = pack_dup(afr.w);
                acc[0][0] = fma2(a0, b01.x, acc[0][0]);
                acc[0][1] = fma2(a0, b01.y, acc[0][1]);
                acc[0][2] = fma2(a0, b23.x, acc[0][2]);
                acc[0][3] = fma2(a0, b23.y, acc[0][3]);
                acc[1][0] = fma2(a1, b01.x, acc[1][0]);
                acc[1][1] = fma2(a1, b01.y, acc[1][1]);
                acc[1][2] = fma2(a1, b23.x, acc[1][2]);
                acc[1][3] = fma2(a1, b23.y, acc[1][3]);
                acc[2][0] = fma2(a2, b01.x, acc[2][0]);
                acc[2][1] = fma2(a2, b01.y, acc[2][1]);
                acc[2][2] = fma2(a2, b23.x, acc[2][2]);
                acc[2][3] = fma2(a2, b23.y, acc[2][3]);
                acc[3][0] = fma2(a3, b01.x, acc[3][0]);
                acc[3][1] = fma2(a3, b01.y, acc[3][1]);
                acc[3][2] = fma2(a3, b23.x, acc[3][2]);
                acc[3][3] = fma2(a3, b23.y, acc[3][3]);
            }
            __syncthreads();
        }

        // epilogue for this N-chunk: tanh(p + q) * V, reduce over the 8 cols,
        // then across the 16 tx lanes, accumulate into es[row].
        const int nb = n0 + tx * 8;
#pragma unroll
        for (int i = 0; i < 4; ++i) {
            float s = 0.f;
#pragma unroll
            for (int jp = 0; jp < 4; ++jp) {
                float2 p = unpack2(acc[i][jp]);
                int n = nb + jp * 2;
                s += tanh_fast(p.x + qs[n])     * Vs[n];
                s += tanh_fast(p.y + qs[n + 1]) * Vs[n + 1];
            }
#pragma unroll
            for (int off = 1; off < 16; off <<= 1)
                s += __shfl_xor_sync(0xffffffffu, s, off);
            if (tx == 0) es[ty * 4 + i] += s;
        }
    }
    __syncthreads();

    if (tid < TM) {
        int s_idx = row0 + tid;
        float e = es[tid];
        g_energy[b * S_ + s_idx] = (s_idx < lens[b]) ? e : NEG_INF_V;
    }
}

// ---------------- K3: per-batch softmax stats ----------------
__global__ __launch_bounds__(256) void stats_kernel() {
    int b = blockIdx.x;
    int tid = threadIdx.x;
    __shared__ float red[256];
    const float* e = &g_energy[b * S_];

    float mx = -3.4e38f;
    for (int s = tid; s < S_; s += 256) mx = fmaxf(mx, e[s]);
    red[tid] = mx;
    __syncthreads();
    for (int o = 128; o > 0; o >>= 1) {
        if (tid < o) red[tid] = fmaxf(red[tid], red[tid + o]);
        __syncthreads();
    }
    mx = red[0];
    __syncthreads();

    float sm = 0.f;
    for (int s = tid; s < S_; s += 256) sm += __expf(e[s] - mx);
    red[tid] = sm;
    __syncthreads();
    for (int o = 128; o > 0; o >>= 1) {
        if (tid < o) red[tid] += red[tid + o];
        __syncthreads();
    }
    if (tid == 0) {
        g_mx[b] = mx;
        g_invden[b] = 1.0f / red[0];
    }
}

// ---------------- K4: zero the output (harness poisons it) ----------------
__global__ void zero_kernel(float* __restrict__ out) {
    out[blockIdx.x * 1024 + threadIdx.x] = 0.f;
}

// ---------------- K5: context = sum_s attn[s] * enc[b,s,:] ----------------
// grid = B * 32 chunks of 64 rows; skip fully-masked chunks.
__global__ __launch_bounds__(256) void context_kernel(const float* __restrict__ enc,
                                                      const int* __restrict__ lens,
                                                      float* __restrict__ out) {
    const int b     = blockIdx.x >> 5;
    const int chunk = blockIdx.x & 31;
    const int row0  = chunk * 64;
    const int len   = lens[b];
    if (row0 >= len) return;  // every weight in this chunk is exactly 0

    __shared__ float ws[64];
    const int tid = threadIdx.x;
    if (tid < 64) {
        float e = g_energy[b * S_ + row0 + tid];
        ws[tid] = __expf(e - g_mx[b]) * g_invden[b];
    }
    __syncthreads();

    const int smax = min(64, len - row0);
    const float* base = enc + ((size_t)b * S_ + row0) * H_;
    float c0 = 0.f, c1 = 0.f;
#pragma unroll 8
    for (int s = 0; s < smax; ++s) {
        float w = ws[s];
        c0 += w * base[(size_t)s * H_ + tid];
        c1 += w * base[(size_t)s * H_ + tid + 256];
    }
    atomicAdd(&out[b * H_ + tid],       c0);
    atomicAdd(&out[b * H_ + tid + 256], c1);
}

// ---------------- launch ----------------
extern "C" void kernel_launch(void* const* d_in, const int* in_sizes, int n_in,
                              void* d_out, int out_size) {
    const float* dec  = (const float*)d_in[0];  // output        [B,1,H] f32
    const float* enc  = (const float*)d_in[1];  // encoder_outputs [B,S,H] f32
    const int*   lens = (const int*)d_in[2];    // lengths [B] i32
    const float* W1   = (const float*)d_in[3];  // [H,H]
    const float* W2   = (const float*)d_in[4];  // [H,H]
    const float* V    = (const float*)d_in[5];  // [H,1]
    float* out = (float*)d_out;                 // context [B,H] f32

    qproj_kernel<<<B_, 512>>>(dec, W2);
    energy_kernel<<<B_ * (S_ / 64), 256>>>(enc, W1, V, lens);
    stats_kernel<<<B_, 256>>>();
    zero_kernel<<<(B_ * H_) / 1024, 1024>>>(out);
    context_kernel<<<B_ * (S_ / 64), 256>>>(enc, lens, out);
}

// round 3
// speedup vs baseline: 4.6194x; 4.6194x over previous
#include <cuda_runtime.h>
#include <cuda_bf16.h>
#include <cstdint>
#include <cstddef>

#define B_ 64
#define S_ 2048
#define H_ 512
#define NEG_INF_V (-1e10f)

// ---------------- scratch (no allocations allowed) ----------------
__device__ float g_q[B_ * H_];             // query projection [B,H]
__device__ float g_energy[B_ * S_];        // energy accumulators / masked energies
__device__ float g_mx[B_];
__device__ float g_invden[B_];
__device__ __nv_bfloat16 g_w1tH[H_ * H_];  // W1^T hi  [n][k]
__device__ __nv_bfloat16 g_w1tL[H_ * H_];  // W1^T lo  [n][k]

// ---------------- helpers ----------------
__device__ __forceinline__ uint32_t smem_u32(const void* p) {
    uint32_t a;
    asm("{ .reg .u64 t; cvta.to.shared.u64 t, %1; cvt.u32.u64 %0, t; }" : "=r"(a) : "l"(p));
    return a;
}
#define SW128(o) ((o) ^ (((o) >> 3) & 0x70))

__device__ __forceinline__ uint32_t cvt2(float lo, float hi) {  // bf16x2 {hi:hi, lo:lo}
    uint32_t r;
    asm("cvt.rn.bf16x2.f32 %0, %1, %2;" : "=r"(r) : "f"(hi), "f"(lo));
    return r;
}
__device__ __forceinline__ float bflo(uint32_t p) { return __uint_as_float(p << 16); }
__device__ __forceinline__ float bfhi(uint32_t p) { return __uint_as_float(p & 0xffff0000u); }

__device__ __forceinline__ float tanh_fast(float x) {
    float e = __expf(2.0f * x);
    return 1.0f - __fdividef(2.0f, e + 1.0f);
}

__device__ __forceinline__ void cp16(uint32_t dst, const void* src) {
    asm volatile("cp.async.cg.shared.global [%0], [%1], 16;" :: "r"(dst), "l"(src) : "memory");
}
__device__ __forceinline__ void cp_commit() {
    asm volatile("cp.async.commit_group;" ::: "memory");
}
__device__ __forceinline__ void cp_wait1() {
    asm volatile("cp.async.wait_group 1;" ::: "memory");
}
__device__ __forceinline__ void cp_wait0() {
    asm volatile("cp.async.wait_group 0;" ::: "memory");
}
__device__ __forceinline__ void ldmx4(uint32_t* r, uint32_t addr) {
    asm volatile("ldmatrix.sync.aligned.m8n8.x4.shared.b16 {%0,%1,%2,%3}, [%4];"
                 : "=r"(r[0]), "=r"(r[1]), "=r"(r[2]), "=r"(r[3]) : "r"(addr));
}
__device__ __forceinline__ void mma16816(float* d, const uint32_t* a, uint32_t b0, uint32_t b1) {
    asm volatile(
        "mma.sync.aligned.m16n8k16.row.col.f32.bf16.bf16.f32 "
        "{%0,%1,%2,%3}, {%4,%5,%6,%7}, {%8,%9}, {%0,%1,%2,%3};"
        : "+f"(d[0]), "+f"(d[1]), "+f"(d[2]), "+f"(d[3])
        : "r"(a[0]), "r"(a[1]), "r"(a[2]), "r"(a[3]), "r"(b0), "r"(b1));
}

// split 8 fp32 -> bf16 hi (uint4) + bf16 lo (uint4)
__device__ __forceinline__ void split8(const float* f, uint4& Hh, uint4& Ll) {
    uint32_t h0 = cvt2(f[0], f[1]), h1 = cvt2(f[2], f[3]);
    uint32_t h2 = cvt2(f[4], f[5]), h3 = cvt2(f[6], f[7]);
    Hh = make_uint4(h0, h1, h2, h3);
    Ll = make_uint4(cvt2(f[0] - bflo(h0), f[1] - bfhi(h0)),
                    cvt2(f[2] - bflo(h1), f[3] - bfhi(h1)),
                    cvt2(f[4] - bflo(h2), f[5] - bfhi(h2)),
                    cvt2(f[6] - bflo(h3), f[7] - bfhi(h3)));
}

// ---------------- K0: W1 -> transposed bf16 hi/lo ----------------
__global__ __launch_bounds__(256) void w1conv_kernel(const float* __restrict__ W1) {
    int idx = blockIdx.x * 256 + threadIdx.x;   // idx = n*512 + k
    int n = idx >> 9, k = idx & 511;
    float x = W1[(size_t)k * H_ + n];
    __nv_bfloat16 h = __float2bfloat16(x);
    g_w1tH[idx] = h;
    g_w1tL[idx] = __float2bfloat16(x - __bfloat162float(h));
}

// ---------------- K1: q[b] = dec[b] @ W2 ----------------
__global__ __launch_bounds__(512) void qproj_kernel(const float* __restrict__ dec,
                                                    const float* __restrict__ W2) {
    int b = blockIdx.x;
    __shared__ float xs[H_];
    xs[threadIdx.x] = dec[b * H_ + threadIdx.x];
    __syncthreads();
    float acc = 0.f;
#pragma unroll 8
    for (int h = 0; h < H_; ++h)
        acc += xs[h] * W2[(size_t)h * H_ + threadIdx.x];
    g_q[b * H_ + threadIdx.x] = acc;
}

// ---------------- K2a: zero energy accumulators ----------------
__global__ void zero_energy_kernel() {
    g_energy[blockIdx.x * 1024 + threadIdx.x] = 0.f;
}

// ---------------- K2: mma.sync energy GEMM ----------------
// CTA: 128 enc rows x 128 W1 cols, K=512 in chunks of 64. 8 warps, warp tile 32x64.
// 3-term bf16 split: D = Ah*Bh + Ah*Bl + Al*Bh, fp32 accum.
#define STG    65536
#define OFF_AH 0
#define OFF_AL 16384
#define OFF_BH 32768
#define OFF_BL 49152
#define DSMEM  (1024 + 2 * STG)   // 132096

__device__ __forceinline__ uint32_t ldm_addr(uint32_t base, int rowf, int kq, int lane) {
    int mi = lane >> 3, li = lane & 7;
    int r  = rowf + ((mi & 1) << 3) + li;
    int kb = (kq << 5) + ((mi >> 1) << 4);
    return base + SW128((uint32_t)(r * 128 + kb));
}

__global__ __launch_bounds__(256, 1) void energy_kernel(const float* __restrict__ enc,
                                                        const float* __restrict__ Vv,
                                                        const int* __restrict__ lens) {
    // grid: b*64 + tile*4 + nc  (adjacent nc share the A tile -> L2 reuse)
    const int nc   = blockIdx.x & 3;
    const int tile = (blockIdx.x >> 2) & 15;
    const int b    = blockIdx.x >> 6;
    const int row0 = tile << 7;
    const int n0   = nc << 7;
    const int len  = lens[b];
    if (row0 >= len) return;   // fully masked tile: weights are exactly 0 downstream

    extern __shared__ char dsm[];
    __shared__ float qs[128], Vs[128], es[128];

    const int tid  = threadIdx.x;
    const int wid  = tid >> 5;
    const int lane = tid & 31;
    const int mbase = (wid >> 1) << 5;   // warp M offset (0..96)
    const int nbase = (wid & 1) << 6;    // warp N offset (0 or 64)

    const uint32_t dynB = smem_u32(dsm);
    const uint32_t tb   = (dynB + 1023u) & ~1023u;
    char* tp = dsm + (tb - dynB);

    if (tid < 128) {
        qs[tid] = g_q[b * H_ + n0 + tid];
        Vs[tid] = Vv[n0 + tid];
        es[tid] = 0.f;
    }

    const float* Abase = enc + ((size_t)b * S_ + row0) * H_;
    const __nv_bfloat16* whb = g_w1tH + (size_t)n0 * H_;
    const __nv_bfloat16* wlb = g_w1tL + (size_t)n0 * H_;

    const int r  = tid >> 1;          // row (A) / n-row (B) handled by this thread
    const int kh = (tid & 1) << 5;    // k offset 0 or 32

    float acc[2][8][4];
#pragma unroll
    for (int i = 0; i < 2; ++i)
#pragma unroll
        for (int j = 0; j < 8; ++j)
#pragma unroll
            for (int q = 0; q < 4; ++q) acc[i][j][q] = 0.f;

    // ---- prologue: B cp.async stage0, A LDG stage0 ----
    {
        const __nv_bfloat16* sh = whb + (size_t)r * H_ + kh;
        const __nv_bfloat16* sl = wlb + (size_t)r * H_ + kh;
#pragma unroll
        for (int jj = 0; jj < 4; ++jj) {
            uint32_t off = SW128((uint32_t)(r * 128 + (kh + jj * 8) * 2));
            cp16(tb + OFF_BH + off, sh + jj * 8);
            cp16(tb + OFF_BL + off, sl + jj * 8);
        }
        cp_commit();
    }
    float areg[32];
    {
        const float* p = Abase + (size_t)r * H_ + kh;
#pragma unroll
        for (int j = 0; j < 8; ++j) *(float4*)&areg[j * 4] = *(const float4*)(p + j * 4);
    }
    __syncthreads();   // covers qs/Vs/es init too

    for (int kc = 0; kc < 8; ++kc) {
        const int buf = kc & 1;
        const uint32_t sb = tb + buf * STG;
        char* sp = tp + buf * STG;

        // store A (convert fp32 -> bf16 hi/lo, swizzled)
#pragma unroll
        for (int jj = 0; jj < 4; ++jj) {
            uint4 Hh, Ll;
            split8(&areg[jj * 8], Hh, Ll);
            uint32_t off = SW128((uint32_t)(r * 128 + (kh + jj * 8) * 2));
            *(uint4*)(sp + OFF_AH + off) = Hh;
            *(uint4*)(sp + OFF_AL + off) = Ll;
        }
        // prefetch next B
        if (kc < 7) {
            const int kt = (kc + 1) << 6;
            const __nv_bfloat16* sh = whb + (size_t)r * H_ + kt + kh;
            const __nv_bfloat16* sl = wlb + (size_t)r * H_ + kt + kh;
            const uint32_t nb = tb + (buf ^ 1) * STG;
#pragma unroll
            for (int jj = 0; jj < 4; ++jj) {
                uint32_t off = SW128((uint32_t)(r * 128 + (kh + jj * 8) * 2));
                cp16(nb + OFF_BH + off, sh + jj * 8);
                cp16(nb + OFF_BL + off, sl + jj * 8);
            }
            cp_commit();
            cp_wait1();
        } else {
            cp_wait0();
        }
        __syncthreads();

        // prefetch next A into regs (overlaps with mma)
        if (kc < 7) {
            const float* p = Abase + (size_t)r * H_ + ((kc + 1) << 6) + kh;
#pragma unroll
            for (int j = 0; j < 8; ++j) *(float4*)&areg[j * 4] = *(const float4*)(p + j * 4);
        }

        // ---- mma over this stage ----
        const uint32_t aH = sb + OFF_AH, aL = sb + OFF_AL;
        const uint32_t bH = sb + OFF_BH, bL = sb + OFF_BL;
#pragma unroll
        for (int kq = 0; kq < 4; ++kq) {
            uint32_t ah[2][4], al[2][4], bh[4][4], bl[4][4];
#pragma unroll
            for (int mt = 0; mt < 2; ++mt) {
                ldmx4(ah[mt], ldm_addr(aH, mbase + mt * 16, kq, lane));
                ldmx4(al[mt], ldm_addr(aL, mbase + mt * 16, kq, lane));
            }
#pragma unroll
            for (int nt2 = 0; nt2 < 4; ++nt2) {
                ldmx4(bh[nt2], ldm_addr(bH, nbase + nt2 * 16, kq, lane));
                ldmx4(bl[nt2], ldm_addr(bL, nbase + nt2 * 16, kq, lane));
            }
#pragma unroll
            for (int mt = 0; mt < 2; ++mt) {
#pragma unroll
                for (int nt2 = 0; nt2 < 4; ++nt2) {
                    float* d0 = acc[mt][nt2 * 2];
                    float* d1 = acc[mt][nt2 * 2 + 1];
                    mma16816(d0, ah[mt], bh[nt2][0], bh[nt2][2]);
                    mma16816(d1, ah[mt], bh[nt2][1], bh[nt2][3]);
                    mma16816(d0, ah[mt], bl[nt2][0], bl[nt2][2]);
                    mma16816(d1, ah[mt], bl[nt2][1], bl[nt2][3]);
                    mma16816(d0, al[mt], bh[nt2][0], bh[nt2][2]);
                    mma16816(d1, al[mt], bh[nt2][1], bh[nt2][3]);
                }
            }
        }
        __syncthreads();
    }

    // ---- epilogue: e[row] += sum_col tanh(d + q[col]) * V[col] ----
    const int gid = lane >> 2, t4 = lane & 3;
#pragma unroll
    for (int mt = 0; mt < 2; ++mt) {
        float s0 = 0.f, s1 = 0.f;
#pragma unroll
        for (int nt = 0; nt < 8; ++nt) {
            int c = nbase + nt * 8 + t4 * 2;
            float q0 = qs[c], q1 = qs[c + 1], v0 = Vs[c], v1 = Vs[c + 1];
            float* d = acc[mt][nt];
            s0 += tanh_fast(d[0] + q0) * v0 + tanh_fast(d[1] + q1) * v1;
            s1 += tanh_fast(d[2] + q0) * v0 + tanh_fast(d[3] + q1) * v1;
        }
        s0 += __shfl_xor_sync(0xffffffffu, s0, 1);
        s0 += __shfl_xor_sync(0xffffffffu, s0, 2);
        s1 += __shfl_xor_sync(0xffffffffu, s1, 1);
        s1 += __shfl_xor_sync(0xffffffffu, s1, 2);
        if (t4 == 0) {
            atomicAdd(&es[mbase + mt * 16 + gid], s0);
            atomicAdd(&es[mbase + mt * 16 + gid + 8], s1);
        }
    }
    __syncthreads();
    if (tid < 128)
        atomicAdd(&g_energy[b * S_ + row0 + tid], es[tid]);
}

// ---------------- K3: mask + softmax stats ----------------
__global__ __launch_bounds__(256) void stats_kernel(const int* __restrict__ lens) {
    int b = blockIdx.x;
    int tid = threadIdx.x;
    int len = lens[b];
    __shared__ float red[256];

    float mx = -3.4e38f;
    for (int s = tid; s < S_; s += 256) {
        int i = b * S_ + s;
        float e = (s < len) ? g_energy[i] : NEG_INF_V;
        g_energy[i] = e;
        mx = fmaxf(mx, e);
    }
    red[tid] = mx;
    __syncthreads();
    for (int o = 128; o > 0; o >>= 1) {
        if (tid < o) red[tid] = fmaxf(red[tid], red[tid + o]);
        __syncthreads();
    }
    mx = red[0];
    __syncthreads();

    float sm = 0.f;
    for (int s = tid; s < S_; s += 256) sm += __expf(g_energy[b * S_ + s] - mx);
    red[tid] = sm;
    __syncthreads();
    for (int o = 128; o > 0; o >>= 1) {
        if (tid < o) red[tid] += red[tid + o];
        __syncthreads();
    }
    if (tid == 0) {
        g_mx[b] = mx;
        g_invden[b] = 1.0f / red[0];
    }
}

// ---------------- K4: zero output ----------------
__global__ void zero_kernel(float* __restrict__ out) {
    out[blockIdx.x * 1024 + threadIdx.x] = 0.f;
}

// ---------------- K5: context = sum_s attn[s] * enc[b,s,:] ----------------
__global__ __launch_bounds__(256) void context_kernel(const float* __restrict__ enc,
                                                      const int* __restrict__ lens,
                                                      float* __restrict__ out) {
    const int b     = blockIdx.x >> 5;
    const int chunk = blockIdx.x & 31;
    const int row0  = chunk * 64;
    const int len   = lens[b];
    if (row0 >= len) return;

    __shared__ float ws[64];
    const int tid = threadIdx.x;
    if (tid < 64) {
        float e = g_energy[b * S_ + row0 + tid];
        ws[tid] = __expf(e - g_mx[b]) * g_invden[b];
    }
    __syncthreads();

    const int smax = min(64, len - row0);
    const float* base = enc + ((size_t)b * S_ + row0) * H_;
    float c0 = 0.f, c1 = 0.f;
#pragma unroll 8
    for (int s = 0; s < smax; ++s) {
        float w = ws[s];
        c0 += w * base[(size_t)s * H_ + tid];
        c1 += w * base[(size_t)s * H_ + tid + 256];
    }
    atomicAdd(&out[b * H_ + tid], c0);
    atomicAdd(&out[b * H_ + tid + 256], c1);
}

// ---------------- launch ----------------
extern "C" void kernel_launch(void* const* d_in, const int* in_sizes, int n_in,
                              void* d_out, int out_size) {
    const float* dec  = (const float*)d_in[0];
    const float* enc  = (const float*)d_in[1];
    const int*   lens = (const int*)d_in[2];
    const float* W1   = (const float*)d_in[3];
    const float* W2   = (const float*)d_in[4];
    const float* V    = (const float*)d_in[5];
    float* out = (float*)d_out;

    cudaFuncSetAttribute(energy_kernel,
                         cudaFuncAttributeMaxDynamicSharedMemorySize, DSMEM);

    w1conv_kernel<<<(H_ * H_) / 256, 256>>>(W1);
    qproj_kernel<<<B_, 512>>>(dec, W2);
    zero_energy_kernel<<<(B_ * S_) / 1024, 1024>>>();
    energy_kernel<<<B_ * 64, 256, DSMEM>>>(enc, V, lens);
    stats_kernel<<<B_, 256>>>(lens);
    zero_kernel<<<(B_ * H_) / 1024, 1024>>>(out);
    context_kernel<<<B_ * (S_ / 64), 256>>>(enc, lens, out);
}

// round 4
// speedup vs baseline: 5.1625x; 1.1176x over previous
#include <cuda_runtime.h>
#include <cuda_bf16.h>
#include <cstdint>
#include <cstddef>

#define B_ 64
#define S_ 2048
#define H_ 512
#define NEG_INF_V (-1e10f)

// ---------------- scratch (no allocations allowed) ----------------
__device__ float g_q[B_ * H_];             // query projection [B,H]
__device__ float g_e0[B_ * S_];            // energy partial cols 0..255
__device__ float g_e1[B_ * S_];            // energy partial cols 256..511
__device__ float g_energy[B_ * S_];        // masked energies
__device__ float g_mx[B_];
__device__ float g_invden[B_];
__device__ __nv_bfloat16 g_w1tH[H_ * H_];  // W1^T hi  [n][k]
__device__ __nv_bfloat16 g_w1tL[H_ * H_];  // W1^T lo  [n][k]
__device__ __nv_bfloat16 g_encH[(size_t)B_ * S_ * H_];  // enc hi
__device__ __nv_bfloat16 g_encL[(size_t)B_ * S_ * H_];  // enc lo

// ---------------- helpers ----------------
__device__ __forceinline__ uint32_t smem_u32(const void* p) {
    uint32_t a;
    asm("{ .reg .u64 t; cvta.to.shared.u64 t, %1; cvt.u32.u64 %0, t; }" : "=r"(a) : "l"(p));
    return a;
}
#define SW128(o) ((o) ^ (((o) >> 3) & 0x70))

__device__ __forceinline__ uint32_t cvt2(float lo, float hi) {  // bf16x2
    uint32_t r;
    asm("cvt.rn.bf16x2.f32 %0, %1, %2;" : "=r"(r) : "f"(hi), "f"(lo));
    return r;
}
__device__ __forceinline__ float bflo(uint32_t p) { return __uint_as_float(p << 16); }
__device__ __forceinline__ float bfhi(uint32_t p) { return __uint_as_float(p & 0xffff0000u); }

__device__ __forceinline__ float tanh_fast(float x) {
    float e = __expf(2.0f * x);
    return 1.0f - __fdividef(2.0f, e + 1.0f);
}

__device__ __forceinline__ void cp16(uint32_t dst, const void* src) {
    asm volatile("cp.async.cg.shared.global [%0], [%1], 16;" :: "r"(dst), "l"(src) : "memory");
}
__device__ __forceinline__ void cp_commit() {
    asm volatile("cp.async.commit_group;" ::: "memory");
}
__device__ __forceinline__ void cp_wait1() {
    asm volatile("cp.async.wait_group 1;" ::: "memory");
}
__device__ __forceinline__ void cp_wait0() {
    asm volatile("cp.async.wait_group 0;" ::: "memory");
}
__device__ __forceinline__ void ldmx4(uint32_t* r, uint32_t addr) {
    asm volatile("ldmatrix.sync.aligned.m8n8.x4.shared.b16 {%0,%1,%2,%3}, [%4];"
                 : "=r"(r[0]), "=r"(r[1]), "=r"(r[2]), "=r"(r[3]) : "r"(addr));
}
__device__ __forceinline__ void mma16816(float* d, const uint32_t* a, uint32_t b0, uint32_t b1) {
    asm volatile(
        "mma.sync.aligned.m16n8k16.row.col.f32.bf16.bf16.f32 "
        "{%0,%1,%2,%3}, {%4,%5,%6,%7}, {%8,%9}, {%0,%1,%2,%3};"
        : "+f"(d[0]), "+f"(d[1]), "+f"(d[2]), "+f"(d[3])
        : "r"(a[0]), "r"(a[1]), "r"(a[2]), "r"(a[3]), "r"(b0), "r"(b1));
}

// ---------------- K0a: W1 -> transposed bf16 hi/lo ----------------
__global__ __launch_bounds__(256) void w1conv_kernel(const float* __restrict__ W1) {
    int idx = blockIdx.x * 256 + threadIdx.x;   // idx = n*512 + k
    int n = idx >> 9, k = idx & 511;
    float x = W1[(size_t)k * H_ + n];
    __nv_bfloat16 h = __float2bfloat16(x);
    g_w1tH[idx] = h;
    g_w1tL[idx] = __float2bfloat16(x - __bfloat162float(h));
}

// ---------------- K0b: enc -> bf16 hi/lo (length-aware) ----------------
__global__ __launch_bounds__(256) void encconv_kernel(const float* __restrict__ enc,
                                                      const int* __restrict__ lens) {
    const int b    = blockIdx.x >> 7;      // 128 blocks per batch, 16 rows each
    const int blk  = blockIdx.x & 127;
    const int row0 = blk << 4;
    const int lim  = ((lens[b] + 127) >> 7) << 7;  // tiles that will execute
    if (row0 >= lim) return;

    const size_t base = ((size_t)b * S_ + row0) * H_;
    const float4* src = (const float4*)(enc + base);
    uint2* dh = (uint2*)(g_encH + base);
    uint2* dl = (uint2*)(g_encL + base);
#pragma unroll 4
    for (int i = threadIdx.x; i < 2048; i += 256) {
        float4 v = src[i];
        uint32_t h0 = cvt2(v.x, v.y), h1 = cvt2(v.z, v.w);
        dh[i] = make_uint2(h0, h1);
        dl[i] = make_uint2(cvt2(v.x - bflo(h0), v.y - bfhi(h0)),
                           cvt2(v.z - bflo(h1), v.w - bfhi(h1)));
    }
}

// ---------------- K1: q[b] = dec[b] @ W2 ----------------
__global__ __launch_bounds__(512) void qproj_kernel(const float* __restrict__ dec,
                                                    const float* __restrict__ W2) {
    int b = blockIdx.x;
    __shared__ float xs[H_];
    xs[threadIdx.x] = dec[b * H_ + threadIdx.x];
    __syncthreads();
    float acc = 0.f;
#pragma unroll 8
    for (int h = 0; h < H_; ++h)
        acc += xs[h] * W2[(size_t)h * H_ + threadIdx.x];
    g_q[b * H_ + threadIdx.x] = acc;
}

// ---------------- K2: mma.sync energy GEMM (pure cp.async pipeline) ----------
// CTA: 128 enc rows x 256 W1 cols, K=512 in chunks of 64. 16 warps, warp tile 32x64.
// 3-term bf16 split: D = Ah*Bh + Ah*Bl + Al*Bh, fp32 accum.
#define STG    98304       // per-stage bytes
#define OFF_AH 0
#define OFF_AL 16384
#define OFF_BH 32768
#define OFF_BL 65536
#define DSMEM  (1024 + 2 * STG)   // 197632

__device__ __forceinline__ uint32_t ldm_addr(uint32_t base, int rowf, int kq, int lane) {
    int mi = lane >> 3, li = lane & 7;
    int r  = rowf + ((mi & 1) << 3) + li;
    int kb = (kq << 5) + ((mi >> 1) << 4);
    return base + SW128((uint32_t)(r * 128 + kb));
}

__device__ __forceinline__ void issue_stage(uint32_t sb,
                                            const __nv_bfloat16* aH, const __nv_bfloat16* aL,
                                            const __nv_bfloat16* bH, const __nv_bfloat16* bL,
                                            int kt, int tid) {
    // A: 128 rows x 64 k. thread -> row tid>>2, quarter tid&3 (2 cp16 per array)
    {
        const int r = tid >> 2, q = tid & 3;
        const __nv_bfloat16* s1 = aH + (size_t)r * H_ + kt + q * 16;
        const __nv_bfloat16* s2 = aL + (size_t)r * H_ + kt + q * 16;
        uint32_t o1 = SW128((uint32_t)(r * 128 + q * 32));
        uint32_t o2 = SW128((uint32_t)(r * 128 + q * 32 + 16));
        cp16(sb + OFF_AH + o1, s1);
        cp16(sb + OFF_AH + o2, s1 + 8);
        cp16(sb + OFF_AL + o1, s2);
        cp16(sb + OFF_AL + o2, s2 + 8);
    }
    // B: 256 rows x 64 k. thread -> row tid>>1, half tid&1 (4 cp16 per array)
    {
        const int rn = tid >> 1, h = tid & 1;
        const __nv_bfloat16* s3 = bH + (size_t)rn * H_ + kt + h * 32;
        const __nv_bfloat16* s4 = bL + (size_t)rn * H_ + kt + h * 32;
#pragma unroll
        for (int j = 0; j < 4; ++j) {
            uint32_t o = SW128((uint32_t)(rn * 128 + h * 64 + j * 16));
            cp16(sb + OFF_BH + o, s3 + j * 8);
            cp16(sb + OFF_BL + o, s4 + j * 8);
        }
    }
}

__global__ __launch_bounds__(512, 1) void energy_kernel(const float* __restrict__ Vv,
                                                        const int* __restrict__ lens) {
    // grid: b*32 + tile*2 + nc
    const int nc   = blockIdx.x & 1;
    const int tile = (blockIdx.x >> 1) & 15;
    const int b    = blockIdx.x >> 5;
    const int row0 = tile << 7;
    const int n0   = nc << 8;
    if (row0 >= lens[b]) return;   // fully masked tile

    extern __shared__ char dsm[];
    __shared__ float qs[256], Vs[256], es[128];

    const int tid  = threadIdx.x;
    const int wid  = tid >> 5;
    const int lane = tid & 31;
    const int mbase = (wid & 3) << 5;   // 0..96
    const int nbase = (wid >> 2) << 6;  // 0..192

    const uint32_t dynB = smem_u32(dsm);
    const uint32_t tb   = (dynB + 1023u) & ~1023u;

    if (tid < 256) {
        qs[tid] = g_q[b * H_ + n0 + tid];
        Vs[tid] = Vv[n0 + tid];
    }
    if (tid < 128) es[tid] = 0.f;

    const __nv_bfloat16* aH = g_encH + ((size_t)b * S_ + row0) * H_;
    const __nv_bfloat16* aL = g_encL + ((size_t)b * S_ + row0) * H_;
    const __nv_bfloat16* bH = g_w1tH + (size_t)n0 * H_;
    const __nv_bfloat16* bL = g_w1tL + (size_t)n0 * H_;

    float acc[2][8][4];
#pragma unroll
    for (int i = 0; i < 2; ++i)
#pragma unroll
        for (int j = 0; j < 8; ++j)
#pragma unroll
            for (int q = 0; q < 4; ++q) acc[i][j][q] = 0.f;

    issue_stage(tb, aH, aL, bH, bL, 0, tid);
    cp_commit();

    for (int kc = 0; kc < 8; ++kc) {
        const int buf = kc & 1;
        const uint32_t sb = tb + buf * STG;
        if (kc < 7) {
            issue_stage(tb + (buf ^ 1) * STG, aH, aL, bH, bL, (kc + 1) << 6, tid);
            cp_commit();
            cp_wait1();
        } else {
            cp_wait0();
        }
        __syncthreads();

        const uint32_t aHs = sb + OFF_AH, aLs = sb + OFF_AL;
        const uint32_t bHs = sb + OFF_BH, bLs = sb + OFF_BL;
#pragma unroll
        for (int kq = 0; kq < 4; ++kq) {
            uint32_t ah[2][4], al[2][4];
            ldmx4(ah[0], ldm_addr(aHs, mbase,      kq, lane));
            ldmx4(ah[1], ldm_addr(aHs, mbase + 16, kq, lane));
            ldmx4(al[0], ldm_addr(aLs, mbase,      kq, lane));
            ldmx4(al[1], ldm_addr(aLs, mbase + 16, kq, lane));
#pragma unroll
            for (int p = 0; p < 2; ++p) {
                uint32_t bh[2][4], bl[2][4];
#pragma unroll
                for (int j = 0; j < 2; ++j) {
                    ldmx4(bh[j], ldm_addr(bHs, nbase + (p * 2 + j) * 16, kq, lane));
                    ldmx4(bl[j], ldm_addr(bLs, nbase + (p * 2 + j) * 16, kq, lane));
                }
#pragma unroll
                for (int mt = 0; mt < 2; ++mt) {
#pragma unroll
                    for (int j = 0; j < 2; ++j) {
                        const int nt2 = p * 2 + j;
                        float* d0 = acc[mt][nt2 * 2];
                        float* d1 = acc[mt][nt2 * 2 + 1];
                        mma16816(d0, ah[mt], bh[j][0], bh[j][2]);
                        mma16816(d1, ah[mt], bh[j][1], bh[j][3]);
                        mma16816(d0, ah[mt], bl[j][0], bl[j][2]);
                        mma16816(d1, ah[mt], bl[j][1], bl[j][3]);
                        mma16816(d0, al[mt], bh[j][0], bh[j][2]);
                        mma16816(d1, al[mt], bh[j][1], bh[j][3]);
                    }
                }
            }
        }
        __syncthreads();
    }

    // ---- epilogue: e[row] += sum_col tanh(d + q[col]) * V[col] ----
    const int gid = lane >> 2, t4 = lane & 3;
#pragma unroll
    for (int mt = 0; mt < 2; ++mt) {
        float s0 = 0.f, s1 = 0.f;
#pragma unroll
        for (int nt = 0; nt < 8; ++nt) {
            int c = nbase + nt * 8 + t4 * 2;
            float q0 = qs[c], q1 = qs[c + 1], v0 = Vs[c], v1 = Vs[c + 1];
            float* d = acc[mt][nt];
            s0 += tanh_fast(d[0] + q0) * v0 + tanh_fast(d[1] + q1) * v1;
            s1 += tanh_fast(d[2] + q0) * v0 + tanh_fast(d[3] + q1) * v1;
        }
        s0 += __shfl_xor_sync(0xffffffffu, s0, 1);
        s0 += __shfl_xor_sync(0xffffffffu, s0, 2);
        s1 += __shfl_xor_sync(0xffffffffu, s1, 1);
        s1 += __shfl_xor_sync(0xffffffffu, s1, 2);
        if (t4 == 0) {
            atomicAdd(&es[mbase + mt * 16 + gid], s0);
            atomicAdd(&es[mbase + mt * 16 + gid + 8], s1);
        }
    }
    __syncthreads();
    if (tid < 128)
        (nc ? g_e1 : g_e0)[b * S_ + row0 + tid] = es[tid];
}

// ---------------- K3: combine halves, mask, softmax stats ----------------
__global__ __launch_bounds__(256) void stats_kernel(const int* __restrict__ lens) {
    int b = blockIdx.x;
    int tid = threadIdx.x;
    int len = lens[b];
    __shared__ float red[256];

    float mx = -3.4e38f;
    for (int s = tid; s < S_; s += 256) {
        int i = b * S_ + s;
        float e = (s < len) ? (g_e0[i] + g_e1[i]) : NEG_INF_V;
        g_energy[i] = e;
        mx = fmaxf(mx, e);
    }
    red[tid] = mx;
    __syncthreads();
    for (int o = 128; o > 0; o >>= 1) {
        if (tid < o) red[tid] = fmaxf(red[tid], red[tid + o]);
        __syncthreads();
    }
    mx = red[0];
    __syncthreads();

    float sm = 0.f;
    for (int s = tid; s < S_; s += 256) sm += __expf(g_energy[b * S_ + s] - mx);
    red[tid] = sm;
    __syncthreads();
    for (int o = 128; o > 0; o >>= 1) {
        if (tid < o) red[tid] += red[tid + o];
        __syncthreads();
    }
    if (tid == 0) {
        g_mx[b] = mx;
        g_invden[b] = 1.0f / red[0];
    }
}

// ---------------- K4: zero output ----------------
__global__ void zero_kernel(float* __restrict__ out) {
    out[blockIdx.x * 1024 + threadIdx.x] = 0.f;
}

// ---------------- K5: context = sum_s attn[s] * enc[b,s,:] ----------------
__global__ __launch_bounds__(256) void context_kernel(const float* __restrict__ enc,
                                                      const int* __restrict__ lens,
                                                      float* __restrict__ out) {
    const int b     = blockIdx.x >> 5;
    const int chunk = blockIdx.x & 31;
    const int row0  = chunk * 64;
    const int len   = lens[b];
    if (row0 >= len) return;

    __shared__ float ws[64];
    const int tid = threadIdx.x;
    if (tid < 64) {
        float e = g_energy[b * S_ + row0 + tid];
        ws[tid] = __expf(e - g_mx[b]) * g_invden[b];
    }
    __syncthreads();

    const int smax = min(64, len - row0);
    const float* base = enc + ((size_t)b * S_ + row0) * H_;
    float c0 = 0.f, c1 = 0.f;
#pragma unroll 8
    for (int s = 0; s < smax; ++s) {
        float w = ws[s];
        c0 += w * base[(size_t)s * H_ + tid];
        c1 += w * base[(size_t)s * H_ + tid + 256];
    }
    atomicAdd(&out[b * H_ + tid], c0);
    atomicAdd(&out[b * H_ + tid + 256], c1);
}

// ---------------- launch ----------------
extern "C" void kernel_launch(void* const* d_in, const int* in_sizes, int n_in,
                              void* d_out, int out_size) {
    const float* dec  = (const float*)d_in[0];
    const float* enc  = (const float*)d_in[1];
    const int*   lens = (const int*)d_in[2];
    const float* W1   = (const float*)d_in[3];
    const float* W2   = (const float*)d_in[4];
    const float* V    = (const float*)d_in[5];
    float* out = (float*)d_out;

    cudaFuncSetAttribute(energy_kernel,
                         cudaFuncAttributeMaxDynamicSharedMemorySize, DSMEM);

    w1conv_kernel<<<(H_ * H_) / 256, 256>>>(W1);
    encconv_kernel<<<B_ * 128, 256>>>(enc, lens);
    qproj_kernel<<<B_, 512>>>(dec, W2);
    energy_kernel<<<B_ * 32, 512, DSMEM>>>(V, lens);
    stats_kernel<<<B_, 256>>>(lens);
    zero_kernel<<<(B_ * H_) / 1024, 1024>>>(out);
    context_kernel<<<B_ * (S_ / 64), 256>>>(enc, lens, out);
}

// round 5
// speedup vs baseline: 9.9222x; 1.9220x over previous
#include <cuda_runtime.h>
#include <cuda_fp16.h>
#include <cstdint>
#include <cstddef>

#define B_ 64
#define S_ 2048
#define H_ 512
#define NEG_INF_V (-1e10f)

// ---------------- scratch (no allocations allowed) ----------------
__device__ float g_q[B_ * H_];            // query projection [B,H]
__device__ float g_ep[4][B_ * S_];        // energy partials per n-chunk
__device__ float g_energy[B_ * S_];       // masked energies
__device__ float g_mx[B_];
__device__ float g_invden[B_];
__device__ __half g_w1tF[H_ * H_];        // W1^T fp16 [n][k]
__device__ __half g_encF[(size_t)B_ * S_ * H_];  // enc fp16

// ---------------- helpers ----------------
__device__ __forceinline__ uint32_t smem_u32(const void* p) {
    uint32_t a;
    asm("{ .reg .u64 t; cvta.to.shared.u64 t, %1; cvt.u32.u64 %0, t; }" : "=r"(a) : "l"(p));
    return a;
}
#define SW128(o) ((o) ^ (((o) >> 3) & 0x70))

__device__ __forceinline__ uint32_t cvtf2(float lo, float hi) {  // f16x2 {hi,lo}
    uint32_t r;
    asm("cvt.rn.f16x2.f32 %0, %1, %2;" : "=r"(r) : "f"(hi), "f"(lo));
    return r;
}
__device__ __forceinline__ float tanh_fast(float x) {
    float e = __expf(2.0f * x);
    return 1.0f - __fdividef(2.0f, e + 1.0f);
}
__device__ __forceinline__ void cp16(uint32_t dst, const void* src) {
    asm volatile("cp.async.cg.shared.global [%0], [%1], 16;" :: "r"(dst), "l"(src) : "memory");
}
__device__ __forceinline__ void cp_commit() {
    asm volatile("cp.async.commit_group;" ::: "memory");
}
__device__ __forceinline__ void cp_wait1() {
    asm volatile("cp.async.wait_group 1;" ::: "memory");
}
__device__ __forceinline__ void cp_wait0() {
    asm volatile("cp.async.wait_group 0;" ::: "memory");
}
__device__ __forceinline__ void ldmx4(uint32_t* r, uint32_t addr) {
    asm volatile("ldmatrix.sync.aligned.m8n8.x4.shared.b16 {%0,%1,%2,%3}, [%4];"
                 : "=r"(r[0]), "=r"(r[1]), "=r"(r[2]), "=r"(r[3]) : "r"(addr));
}
__device__ __forceinline__ void mma16816(float* d, const uint32_t* a, uint32_t b0, uint32_t b1) {
    asm volatile(
        "mma.sync.aligned.m16n8k16.row.col.f32.f16.f16.f32 "
        "{%0,%1,%2,%3}, {%4,%5,%6,%7}, {%8,%9}, {%0,%1,%2,%3};"
        : "+f"(d[0]), "+f"(d[1]), "+f"(d[2]), "+f"(d[3])
        : "r"(a[0]), "r"(a[1]), "r"(a[2]), "r"(a[3]), "r"(b0), "r"(b1));
}

// ---------------- K0a: W1 -> transposed fp16 ----------------
__global__ __launch_bounds__(256) void w1conv_kernel(const float* __restrict__ W1) {
    int idx = blockIdx.x * 256 + threadIdx.x;   // idx = n*512 + k
    int n = idx >> 9, k = idx & 511;
    g_w1tF[idx] = __float2half(W1[(size_t)k * H_ + n]);
}

// ---------------- K0b: enc -> fp16 (length-aware) ----------------
__global__ __launch_bounds__(256) void encconv_kernel(const float* __restrict__ enc,
                                                      const int* __restrict__ lens) {
    const int b    = blockIdx.x >> 7;      // 128 blocks per batch, 16 rows each
    const int blk  = blockIdx.x & 127;
    const int row0 = blk << 4;
    const int lim  = ((lens[b] + 127) >> 7) << 7;
    if (row0 >= lim) return;

    const size_t base = ((size_t)b * S_ + row0) * H_;
    const float4* src = (const float4*)(enc + base);
    uint2* dh = (uint2*)(g_encF + base);
#pragma unroll 4
    for (int i = threadIdx.x; i < 2048; i += 256) {
        float4 v = src[i];
        dh[i] = make_uint2(cvtf2(v.x, v.y), cvtf2(v.z, v.w));
    }
}

// ---------------- K1: q[b] = dec[b] @ W2 (fp32, exact) ----------------
__global__ __launch_bounds__(512) void qproj_kernel(const float* __restrict__ dec,
                                                    const float* __restrict__ W2) {
    int b = blockIdx.x;
    __shared__ float xs[H_];
    xs[threadIdx.x] = dec[b * H_ + threadIdx.x];
    __syncthreads();
    float acc = 0.f;
#pragma unroll 8
    for (int h = 0; h < H_; ++h)
        acc += xs[h] * W2[(size_t)h * H_ + threadIdx.x];
    g_q[b * H_ + threadIdx.x] = acc;
}

// ---------------- K2: fp16 mma.sync energy GEMM ----------------
// CTA: 128 rows x 128 cols, K=512 in 8 chunks of 64, 3-stage cp.async pipeline,
// 8 warps (warp tile 32x64), 2 CTAs/SM.
#define STG    32768
#define OFF_B  16384
#define DSMEM  (1024 + 3 * STG)   // 99328

__device__ __forceinline__ uint32_t ldm_addr(uint32_t base, int rowf, int kq, int lane) {
    int mi = lane >> 3, li = lane & 7;
    int r  = rowf + ((mi & 1) << 3) + li;
    int kb = (kq << 5) + ((mi >> 1) << 4);
    return base + SW128((uint32_t)(r * 128 + kb));
}

__global__ __launch_bounds__(256, 2) void energy_kernel(const float* __restrict__ Vv,
                                                        const int* __restrict__ lens) {
    // grid: b*64 + tile*4 + nc  (adjacent nc share the A tile in L2)
    const int nc   = blockIdx.x & 3;
    const int tile = (blockIdx.x >> 2) & 15;
    const int b    = blockIdx.x >> 6;
    const int row0 = tile << 7;
    const int n0   = nc << 7;
    if (row0 >= lens[b]) return;

    extern __shared__ char dsm[];
    __shared__ float qs[128], Vs[128], es[128];

    const int tid  = threadIdx.x;
    const int wid  = tid >> 5;
    const int lane = tid & 31;
    const int mbase = (wid & 3) << 5;   // 0..96
    const int nbase = (wid >> 2) << 6;  // 0 or 64

    const uint32_t dynB = smem_u32(dsm);
    const uint32_t tb   = (dynB + 1023u) & ~1023u;

    if (tid < 128) {
        qs[tid] = g_q[b * H_ + n0 + tid];
        Vs[tid] = Vv[n0 + tid];
        es[tid] = 0.f;
    }

    // per-thread copy slots: r = tid>>1 (0..127), seg = tid&1 (64B half-row)
    const int r = tid >> 1, seg = tid & 1;
    const __half* aSrc = g_encF + ((size_t)b * S_ + row0 + r) * H_ + seg * 32;
    const __half* bSrc = g_w1tF + ((size_t)(n0 + r)) * H_ + seg * 32;
    uint32_t offs[4];
#pragma unroll
    for (int j = 0; j < 4; ++j)
        offs[j] = SW128((uint32_t)(r * 128 + seg * 64 + j * 16));

    float acc[2][8][4];
#pragma unroll
    for (int i = 0; i < 2; ++i)
#pragma unroll
        for (int j = 0; j < 8; ++j)
#pragma unroll
            for (int q = 0; q < 4; ++q) acc[i][j][q] = 0.f;

    // prologue: stages 0,1
#pragma unroll
    for (int s = 0; s < 2; ++s) {
        const uint32_t sb = tb + s * STG;
#pragma unroll
        for (int j = 0; j < 4; ++j) {
            cp16(sb + offs[j],         aSrc + s * 64 + j * 8);
            cp16(sb + OFF_B + offs[j], bSrc + s * 64 + j * 8);
        }
        cp_commit();
    }

#pragma unroll
    for (int kc = 0; kc < 8; ++kc) {
        if (kc < 7) cp_wait1(); else cp_wait0();
        __syncthreads();

        if (kc < 6) {
            const int ns = kc + 2;
            const uint32_t sb = tb + (ns % 3) * STG;
#pragma unroll
            for (int j = 0; j < 4; ++j) {
                cp16(sb + offs[j],         aSrc + ns * 64 + j * 8);
                cp16(sb + OFF_B + offs[j], bSrc + ns * 64 + j * 8);
            }
            cp_commit();
        }

        const uint32_t aB = tb + (kc % 3) * STG;
        const uint32_t bB = aB + OFF_B;
#pragma unroll
        for (int kq = 0; kq < 4; ++kq) {
            uint32_t a0[4], a1[4], bf[4][4];
            ldmx4(a0, ldm_addr(aB, mbase,      kq, lane));
            ldmx4(a1, ldm_addr(aB, mbase + 16, kq, lane));
#pragma unroll
            for (int t = 0; t < 4; ++t)
                ldmx4(bf[t], ldm_addr(bB, nbase + t * 16, kq, lane));
#pragma unroll
            for (int t = 0; t < 4; ++t) {
                mma16816(acc[0][t * 2],     a0, bf[t][0], bf[t][2]);
                mma16816(acc[0][t * 2 + 1], a0, bf[t][1], bf[t][3]);
                mma16816(acc[1][t * 2],     a1, bf[t][0], bf[t][2]);
                mma16816(acc[1][t * 2 + 1], a1, bf[t][1], bf[t][3]);
            }
        }
    }
    __syncthreads();

    // ---- epilogue: e[row] += sum_col tanh(d + q[col]) * V[col] ----
    const int gid = lane >> 2, t4 = lane & 3;
#pragma unroll
    for (int mt = 0; mt < 2; ++mt) {
        float s0 = 0.f, s1 = 0.f;
#pragma unroll
        for (int nt = 0; nt < 8; ++nt) {
            int c = nbase + nt * 8 + t4 * 2;
            float q0 = qs[c], q1 = qs[c + 1], v0 = Vs[c], v1 = Vs[c + 1];
            float* d = acc[mt][nt];
            s0 += tanh_fast(d[0] + q0) * v0 + tanh_fast(d[1] + q1) * v1;
            s1 += tanh_fast(d[2] + q0) * v0 + tanh_fast(d[3] + q1) * v1;
        }
        s0 += __shfl_xor_sync(0xffffffffu, s0, 1);
        s0 += __shfl_xor_sync(0xffffffffu, s0, 2);
        s1 += __shfl_xor_sync(0xffffffffu, s1, 1);
        s1 += __shfl_xor_sync(0xffffffffu, s1, 2);
        if (t4 == 0) {
            atomicAdd(&es[mbase + mt * 16 + gid], s0);
            atomicAdd(&es[mbase + mt * 16 + gid + 8], s1);
        }
    }
    __syncthreads();
    if (tid < 128)
        g_ep[nc][b * S_ + row0 + tid] = es[tid];
}

// ---------------- K3: combine partials, mask, softmax stats ----------------
__global__ __launch_bounds__(256) void stats_kernel(const int* __restrict__ lens) {
    int b = blockIdx.x;
    int tid = threadIdx.x;
    int len = lens[b];
    __shared__ float red[256];

    float mx = -3.4e38f;
    for (int s = tid; s < S_; s += 256) {
        int i = b * S_ + s;
        float e = (s < len) ? (g_ep[0][i] + g_ep[1][i] + g_ep[2][i] + g_ep[3][i])
                            : NEG_INF_V;
        g_energy[i] = e;
        mx = fmaxf(mx, e);
    }
    red[tid] = mx;
    __syncthreads();
    for (int o = 128; o > 0; o >>= 1) {
        if (tid < o) red[tid] = fmaxf(red[tid], red[tid + o]);
        __syncthreads();
    }
    mx = red[0];
    __syncthreads();

    float sm = 0.f;
    for (int s = tid; s < S_; s += 256) sm += __expf(g_energy[b * S_ + s] - mx);
    red[tid] = sm;
    __syncthreads();
    for (int o = 128; o > 0; o >>= 1) {
        if (tid < o) red[tid] += red[tid + o];
        __syncthreads();
    }
    if (tid == 0) {
        g_mx[b] = mx;
        g_invden[b] = 1.0f / red[0];
    }
}

// ---------------- K4: zero output ----------------
__global__ void zero_kernel(float* __restrict__ out) {
    out[blockIdx.x * 1024 + threadIdx.x] = 0.f;
}

// ---------------- K5: context = sum_s attn[s] * enc[b,s,:] ----------------
__global__ __launch_bounds__(256) void context_kernel(const float* __restrict__ enc,
                                                      const int* __restrict__ lens,
                                                      float* __restrict__ out) {
    const int b     = blockIdx.x >> 5;
    const int chunk = blockIdx.x & 31;
    const int row0  = chunk * 64;
    const int len   = lens[b];
    if (row0 >= len) return;

    __shared__ float ws[64];
    const int tid = threadIdx.x;
    if (tid < 64) {
        float e = g_energy[b * S_ + row0 + tid];
        ws[tid] = __expf(e - g_mx[b]) * g_invden[b];
    }
    __syncthreads();

    const int smax = min(64, len - row0);
    const float* base = enc + ((size_t)b * S_ + row0) * H_;
    float c0 = 0.f, c1 = 0.f;
#pragma unroll 8
    for (int s = 0; s < smax; ++s) {
        float w = ws[s];
        c0 += w * base[(size_t)s * H_ + tid];
        c1 += w * base[(size_t)s * H_ + tid + 256];
    }
    atomicAdd(&out[b * H_ + tid], c0);
    atomicAdd(&out[b * H_ + tid + 256], c1);
}

// ---------------- launch ----------------
extern "C" void kernel_launch(void* const* d_in, const int* in_sizes, int n_in,
                              void* d_out, int out_size) {
    const float* dec  = (const float*)d_in[0];
    const float* enc  = (const float*)d_in[1];
    const int*   lens = (const int*)d_in[2];
    const float* W1   = (const float*)d_in[3];
    const float* W2   = (const float*)d_in[4];
    const float* V    = (const float*)d_in[5];
    float* out = (float*)d_out;

    cudaFuncSetAttribute(energy_kernel,
                         cudaFuncAttributeMaxDynamicSharedMemorySize, DSMEM);

    w1conv_kernel<<<(H_ * H_) / 256, 256>>>(W1);
    encconv_kernel<<<B_ * 128, 256>>>(enc, lens);
    qproj_kernel<<<B_, 512>>>(dec, W2);
    energy_kernel<<<B_ * 64, 256, DSMEM>>>(V, lens);
    stats_kernel<<<B_, 256>>>(lens);
    zero_kernel<<<(B_ * H_) / 1024, 1024>>>(out);
    context_kernel<<<B_ * (S_ / 64), 256>>>(enc, lens, out);
}

// round 7
// speedup vs baseline: 10.2020x; 1.0282x over previous
#include <cuda_runtime.h>
#include <cuda_fp16.h>
#include <cstdint>
#include <cstddef>

#define B_ 64
#define S_ 2048
#define H_ 512
#define NEG_INF_V (-1e10f)

// ---------------- scratch (no allocations allowed) ----------------
__device__ float g_q[B_ * H_];            // query projection [B,H]
__device__ float g_ep[4][B_ * S_];        // energy partials per n-chunk
__device__ float g_energy[B_ * S_];       // masked energies
__device__ float g_mx[B_];
__device__ float g_invden[B_];
__device__ __half g_w1tF[H_ * H_];        // W1^T fp16 [n][k]
__device__ __half g_encF[(size_t)B_ * S_ * H_];  // enc fp16

// ---------------- helpers ----------------
__device__ __forceinline__ uint32_t smem_u32(const void* p) {
    uint32_t a;
    asm("{ .reg .u64 t; cvta.to.shared.u64 t, %1; cvt.u32.u64 %0, t; }" : "=r"(a) : "l"(p));
    return a;
}
#define SW128(o) ((o) ^ (((o) >> 3) & 0x70))

__device__ __forceinline__ uint32_t cvtf2(float lo, float hi) {  // f16x2 {hi,lo}
    uint32_t r;
    asm("cvt.rn.f16x2.f32 %0, %1, %2;" : "=r"(r) : "f"(hi), "f"(lo));
    return r;
}
__device__ __forceinline__ float tanh_fast(float x) {
    float e = __expf(2.0f * x);
    return 1.0f - __fdividef(2.0f, e + 1.0f);
}
__device__ __forceinline__ void cp16(uint32_t dst, const void* src) {
    asm volatile("cp.async.cg.shared.global [%0], [%1], 16;" :: "r"(dst), "l"(src) : "memory");
}
__device__ __forceinline__ void cp_commit() {
    asm volatile("cp.async.commit_group;" ::: "memory");
}
__device__ __forceinline__ void cp_wait1() {
    asm volatile("cp.async.wait_group 1;" ::: "memory");
}
__device__ __forceinline__ void cp_wait0() {
    asm volatile("cp.async.wait_group 0;" ::: "memory");
}
__device__ __forceinline__ void ldmx4(uint32_t* r, uint32_t addr) {
    asm volatile("ldmatrix.sync.aligned.m8n8.x4.shared.b16 {%0,%1,%2,%3}, [%4];"
                 : "=r"(r[0]), "=r"(r[1]), "=r"(r[2]), "=r"(r[3]) : "r"(addr));
}
__device__ __forceinline__ void mma16816(float* d, const uint32_t* a, uint32_t b0, uint32_t b1) {
    asm volatile(
        "mma.sync.aligned.m16n8k16.row.col.f32.f16.f16.f32 "
        "{%0,%1,%2,%3}, {%4,%5,%6,%7}, {%8,%9}, {%0,%1,%2,%3};"
        : "+f"(d[0]), "+f"(d[1]), "+f"(d[2]), "+f"(d[3])
        : "r"(a[0]), "r"(a[1]), "r"(a[2]), "r"(a[3]), "r"(b0), "r"(b1));
}

// ---------------- K0: fused prep (encconv | w1conv | qproj) ----------------
__global__ __launch_bounds__(256) void prep_kernel(const float* __restrict__ enc,
                                                   const int* __restrict__ lens,
                                                   const float* __restrict__ W1,
                                                   const float* __restrict__ dec,
                                                   const float* __restrict__ W2) {
    const int blk = blockIdx.x;
    const int tid = threadIdx.x;

    if (blk < 8192) {                       // ---- encconv (16 rows each) ----
        const int b    = blk >> 7;
        const int row0 = (blk & 127) << 4;
        const int lim  = ((lens[b] + 127) >> 7) << 7;
        if (row0 >= lim) return;
        const size_t base = ((size_t)b * S_ + row0) * H_;
        const float4* src = (const float4*)(enc + base);
        uint2* dh = (uint2*)(g_encF + base);
#pragma unroll 4
        for (int i = tid; i < 2048; i += 256) {
            float4 v = src[i];
            dh[i] = make_uint2(cvtf2(v.x, v.y), cvtf2(v.z, v.w));
        }
    } else if (blk < 9216) {                // ---- w1conv ----
        int idx = (blk - 8192) * 256 + tid; // idx = n*512 + k
        int n = idx >> 9, k = idx & 511;
        g_w1tF[idx] = __float2half(W1[(size_t)k * H_ + n]);
    } else {                                // ---- qproj ----
        const int b = blk - 9216;
        __shared__ float xs[H_];
        xs[tid] = dec[b * H_ + tid];
        xs[tid + 256] = dec[b * H_ + tid + 256];
        __syncthreads();
        float a0 = 0.f, a1 = 0.f;
#pragma unroll 8
        for (int h = 0; h < H_; ++h) {
            float x = xs[h];
            a0 += x * W2[(size_t)h * H_ + tid];
            a1 += x * W2[(size_t)h * H_ + tid + 256];
        }
        g_q[b * H_ + tid] = a0;
        g_q[b * H_ + tid + 256] = a1;
    }
}

// ---------------- K1: fp16 mma.sync energy GEMM ----------------
// CTA: 128 rows x 128 cols, K=512 in 8 chunks of 64, 3-stage cp.async pipeline,
// 8 warps (warp tile 32x64), 2 CTAs/SM.
#define STG    32768
#define OFF_B  16384
#define DSMEM  (1024 + 3 * STG)   // 99328

__global__ __launch_bounds__(256, 2) void energy_kernel(const float* __restrict__ Vv,
                                                        const int* __restrict__ lens) {
    // grid: b*64 + tile*4 + nc  (adjacent nc share the A tile in L2)
    const int nc   = blockIdx.x & 3;
    const int tile = (blockIdx.x >> 2) & 15;
    const int b    = blockIdx.x >> 6;
    const int row0 = tile << 7;
    const int n0   = nc << 7;
    if (row0 >= lens[b]) return;

    extern __shared__ char dsm[];
    __shared__ float qs[128], Vs[128], es[128];

    const int tid  = threadIdx.x;
    const int wid  = tid >> 5;
    const int lane = tid & 31;
    const int mbase = (wid & 3) << 5;   // 0..96
    const int nbase = (wid >> 2) << 6;  // 0 or 64

    const uint32_t dynB = smem_u32(dsm);
    const uint32_t tb   = (dynB + 1023u) & ~1023u;

    if (tid < 128) {
        qs[tid] = g_q[b * H_ + n0 + tid];
        Vs[tid] = Vv[n0 + tid];
        es[tid] = 0.f;
    }

    // per-thread cp.async slots: r = tid>>1 (0..127), seg = tid&1 (64B half-row)
    const int r = tid >> 1, seg = tid & 1;
    const __half* aSrc = g_encF + ((size_t)b * S_ + row0 + r) * H_ + seg * 32;
    const __half* bSrc = g_w1tF + ((size_t)(n0 + r)) * H_ + seg * 32;
    uint32_t offs[4];
#pragma unroll
    for (int j = 0; j < 4; ++j)
        offs[j] = SW128((uint32_t)(r * 128 + seg * 64 + j * 16));

    // ldmatrix swizzled base addresses. The un-swizzled offset has bits 5..6
    // clear, so the kq*32 advance folds in with XOR (never ADD: the swizzle's
    // XOR term also occupies bits 5..6 and ADD would carry into the row bits).
    const int rb  = (((lane & 15) >> 3) << 3) + (lane & 7);
    const int c16 = (lane >> 4) << 4;
    const uint32_t aA0 = tb + SW128((uint32_t)((mbase + rb) * 128 + c16));
    const uint32_t aA1 = tb + SW128((uint32_t)((mbase + 16 + rb) * 128 + c16));
    const uint32_t aB0 = tb + OFF_B + SW128((uint32_t)((nbase + rb) * 128 + c16));
    const uint32_t aB1 = tb + OFF_B + SW128((uint32_t)((nbase + 16 + rb) * 128 + c16));
    const uint32_t aB2 = tb + OFF_B + SW128((uint32_t)((nbase + 32 + rb) * 128 + c16));
    const uint32_t aB3 = tb + OFF_B + SW128((uint32_t)((nbase + 48 + rb) * 128 + c16));

    float acc[2][8][4];
#pragma unroll
    for (int i = 0; i < 2; ++i)
#pragma unroll
        for (int j = 0; j < 8; ++j)
#pragma unroll
            for (int q = 0; q < 4; ++q) acc[i][j][q] = 0.f;

    // prologue: stages 0,1
#pragma unroll
    for (int s = 0; s < 2; ++s) {
        const uint32_t sb = tb + s * STG;
#pragma unroll
        for (int j = 0; j < 4; ++j) {
            cp16(sb + offs[j],         aSrc + s * 64 + j * 8);
            cp16(sb + OFF_B + offs[j], bSrc + s * 64 + j * 8);
        }
        cp_commit();
    }

#pragma unroll
    for (int kc = 0; kc < 8; ++kc) {
        if (kc < 7) cp_wait1(); else cp_wait0();
        __syncthreads();

        if (kc < 6) {
            const int ns = kc + 2;
            const uint32_t sb = tb + (ns % 3) * STG;
#pragma unroll
            for (int j = 0; j < 4; ++j) {
                cp16(sb + offs[j],         aSrc + ns * 64 + j * 8);
                cp16(sb + OFF_B + offs[j], bSrc + ns * 64 + j * 8);
            }
            cp_commit();
        }

        const uint32_t so = (kc % 3) * STG;   // stage offset: 32KB-aligned, safe to ADD
#pragma unroll
        for (int kq = 0; kq < 4; ++kq) {
            const uint32_t kk = (uint32_t)(kq << 5);   // bits 5..6: fold with XOR
            uint32_t a0[4], a1[4], bf[4][4];
            ldmx4(a0, (aA0 + so) ^ kk);
            ldmx4(a1, (aA1 + so) ^ kk);
            ldmx4(bf[0], (aB0 + so) ^ kk);
            ldmx4(bf[1], (aB1 + so) ^ kk);
            ldmx4(bf[2], (aB2 + so) ^ kk);
            ldmx4(bf[3], (aB3 + so) ^ kk);
#pragma unroll
            for (int t = 0; t < 4; ++t) {
                mma16816(acc[0][t * 2],     a0, bf[t][0], bf[t][2]);
                mma16816(acc[0][t * 2 + 1], a0, bf[t][1], bf[t][3]);
                mma16816(acc[1][t * 2],     a1, bf[t][0], bf[t][2]);
                mma16816(acc[1][t * 2 + 1], a1, bf[t][1], bf[t][3]);
            }
        }
    }
    __syncthreads();

    // ---- epilogue: e[row] += sum_col tanh(d + q[col]) * V[col] ----
    const int gid = lane >> 2, t4 = lane & 3;
#pragma unroll
    for (int mt = 0; mt < 2; ++mt) {
        float s0 = 0.f, s1 = 0.f;
#pragma unroll
        for (int nt = 0; nt < 8; ++nt) {
            int c = nbase + nt * 8 + t4 * 2;
            float q0 = qs[c], q1 = qs[c + 1], v0 = Vs[c], v1 = Vs[c + 1];
            float* d = acc[mt][nt];
            s0 += tanh_fast(d[0] + q0) * v0 + tanh_fast(d[1] + q1) * v1;
            s1 += tanh_fast(d[2] + q0) * v0 + tanh_fast(d[3] + q1) * v1;
        }
        s0 += __shfl_xor_sync(0xffffffffu, s0, 1);
        s0 += __shfl_xor_sync(0xffffffffu, s0, 2);
        s1 += __shfl_xor_sync(0xffffffffu, s1, 1);
        s1 += __shfl_xor_sync(0xffffffffu, s1, 2);
        if (t4 == 0) {
            atomicAdd(&es[mbase + mt * 16 + gid], s0);
            atomicAdd(&es[mbase + mt * 16 + gid + 8], s1);
        }
    }
    __syncthreads();
    if (tid < 128)
        g_ep[nc][b * S_ + row0 + tid] = es[tid];
}

// ---------------- K2: combine partials, mask, stats, zero out ----------------
__global__ __launch_bounds__(256) void stats_kernel(const int* __restrict__ lens,
                                                    float* __restrict__ out) {
    int b = blockIdx.x;
    int tid = threadIdx.x;
    int len = lens[b];
    __shared__ float red[256];

    out[b * H_ + tid] = 0.f;
    out[b * H_ + tid + 256] = 0.f;

    float mx = -3.4e38f;
    for (int s = tid; s < S_; s += 256) {
        int i = b * S_ + s;
        float e = (s < len) ? (g_ep[0][i] + g_ep[1][i] + g_ep[2][i] + g_ep[3][i])
                            : NEG_INF_V;
        g_energy[i] = e;
        mx = fmaxf(mx, e);
    }
    red[tid] = mx;
    __syncthreads();
    for (int o = 128; o > 0; o >>= 1) {
        if (tid < o) red[tid] = fmaxf(red[tid], red[tid + o]);
        __syncthreads();
    }
    mx = red[0];
    __syncthreads();

    float sm = 0.f;
    for (int s = tid; s < S_; s += 256) sm += __expf(g_energy[b * S_ + s] - mx);
    red[tid] = sm;
    __syncthreads();
    for (int o = 128; o > 0; o >>= 1) {
        if (tid < o) red[tid] += red[tid + o];
        __syncthreads();
    }
    if (tid == 0) {
        g_mx[b] = mx;
        g_invden[b] = 1.0f / red[0];
    }
}

// ---------------- K3: context = sum_s attn[s] * enc_fp16[b,s,:] ----------------
__global__ __launch_bounds__(256) void context_kernel(const int* __restrict__ lens,
                                                      float* __restrict__ out) {
    const int b     = blockIdx.x >> 5;
    const int chunk = blockIdx.x & 31;
    const int row0  = chunk * 64;
    const int len   = lens[b];
    if (row0 >= len) return;

    __shared__ float ws[64];
    const int tid = threadIdx.x;
    if (tid < 64) {
        float e = g_energy[b * S_ + row0 + tid];
        ws[tid] = __expf(e - g_mx[b]) * g_invden[b];
    }
    __syncthreads();

    const int smax = min(64, len - row0);
    const __half2* base = (const __half2*)(g_encF + ((size_t)b * S_ + row0) * H_) + tid;
    float c0 = 0.f, c1 = 0.f;
#pragma unroll 8
    for (int s = 0; s < smax; ++s) {
        float2 f = __half22float2(base[s * 256]);
        float w = ws[s];
        c0 += w * f.x;
        c1 += w * f.y;
    }
    atomicAdd(&out[b * H_ + tid * 2], c0);
    atomicAdd(&out[b * H_ + tid * 2 + 1], c1);
}

// ---------------- launch ----------------
extern "C" void kernel_launch(void* const* d_in, const int* in_sizes, int n_in,
                              void* d_out, int out_size) {
    const float* dec  = (const float*)d_in[0];
    const float* enc  = (const float*)d_in[1];
    const int*   lens = (const int*)d_in[2];
    const float* W1   = (const float*)d_in[3];
    const float* W2   = (const float*)d_in[4];
    const float* V    = (const float*)d_in[5];
    float* out = (float*)d_out;

    cudaFuncSetAttribute(energy_kernel,
                         cudaFuncAttributeMaxDynamicSharedMemorySize, DSMEM);

    prep_kernel<<<9280, 256>>>(enc, lens, W1, dec, W2);
    energy_kernel<<<B_ * 64, 256, DSMEM>>>(V, lens);
    stats_kernel<<<B_, 256>>>(lens, out);
    context_kernel<<<B_ * (S_ / 64), 256>>>(lens, out);
}

// round 8
// speedup vs baseline: 10.5397x; 1.0331x over previous
#include <cuda_runtime.h>
#include <cuda_fp16.h>
#include <cstdint>
#include <cstddef>

#define B_ 64
#define S_ 2048
#define H_ 512
#define NEG_INF_V (-1e10f)

// ---------------- scratch (no allocations allowed) ----------------
__device__ float g_q[B_ * H_];            // query projection [B,H]
__device__ float g_ep[2][B_ * S_];        // energy partials per n-half
__device__ float g_energy[B_ * S_];       // masked energies
__device__ float g_mx[B_];
__device__ float g_invden[B_];
__device__ __half g_w1tF[H_ * H_];        // W1^T fp16 [n][k]
__device__ __half g_encF[(size_t)B_ * S_ * H_];  // enc fp16

// ---------------- helpers ----------------
__device__ __forceinline__ uint32_t smem_u32(const void* p) {
    uint32_t a;
    asm("{ .reg .u64 t; cvta.to.shared.u64 t, %1; cvt.u32.u64 %0, t; }" : "=r"(a) : "l"(p));
    return a;
}
#define SW128(o) ((o) ^ (((o) >> 3) & 0x70))

__device__ __forceinline__ uint32_t cvtf2(float lo, float hi) {  // f16x2 {hi,lo}
    uint32_t r;
    asm("cvt.rn.f16x2.f32 %0, %1, %2;" : "=r"(r) : "f"(hi), "f"(lo));
    return r;
}
__device__ __forceinline__ float tanh_fast(float x) {
    float e = __expf(2.0f * x);
    return 1.0f - __fdividef(2.0f, e + 1.0f);
}
__device__ __forceinline__ void cp16(uint32_t dst, const void* src) {
    asm volatile("cp.async.cg.shared.global [%0], [%1], 16;" :: "r"(dst), "l"(src) : "memory");
}
__device__ __forceinline__ void cp_commit() {
    asm volatile("cp.async.commit_group;" ::: "memory");
}
__device__ __forceinline__ void cp_wait1() {
    asm volatile("cp.async.wait_group 1;" ::: "memory");
}
__device__ __forceinline__ void cp_wait0() {
    asm volatile("cp.async.wait_group 0;" ::: "memory");
}
__device__ __forceinline__ void ldmx4(uint32_t* r, uint32_t addr) {
    asm volatile("ldmatrix.sync.aligned.m8n8.x4.shared.b16 {%0,%1,%2,%3}, [%4];"
                 : "=r"(r[0]), "=r"(r[1]), "=r"(r[2]), "=r"(r[3]) : "r"(addr));
}
__device__ __forceinline__ void mma16816(float* d, const uint32_t* a, uint32_t b0, uint32_t b1) {
    asm volatile(
        "mma.sync.aligned.m16n8k16.row.col.f32.f16.f16.f32 "
        "{%0,%1,%2,%3}, {%4,%5,%6,%7}, {%8,%9}, {%0,%1,%2,%3};"
        : "+f"(d[0]), "+f"(d[1]), "+f"(d[2]), "+f"(d[3])
        : "r"(a[0]), "r"(a[1]), "r"(a[2]), "r"(a[3]), "r"(b0), "r"(b1));
}

// ---------------- K0: fused prep (encconv | w1conv | qproj) ----------------
__global__ __launch_bounds__(256) void prep_kernel(const float* __restrict__ enc,
                                                   const int* __restrict__ lens,
                                                   const float* __restrict__ W1,
                                                   const float* __restrict__ dec,
                                                   const float* __restrict__ W2) {
    const int blk = blockIdx.x;
    const int tid = threadIdx.x;

    if (blk < 8192) {                       // ---- encconv (16 rows each) ----
        const int b    = blk >> 7;
        const int row0 = (blk & 127) << 4;
        const int lim  = ((lens[b] + 127) >> 7) << 7;
        if (row0 >= lim) return;
        const size_t base = ((size_t)b * S_ + row0) * H_;
        const float4* src = (const float4*)(enc + base);
        uint2* dh = (uint2*)(g_encF + base);
#pragma unroll 4
        for (int i = tid; i < 2048; i += 256) {
            float4 v = src[i];
            dh[i] = make_uint2(cvtf2(v.x, v.y), cvtf2(v.z, v.w));
        }
    } else if (blk < 9216) {                // ---- w1conv ----
        int idx = (blk - 8192) * 256 + tid; // idx = n*512 + k
        int n = idx >> 9, k = idx & 511;
        g_w1tF[idx] = __float2half(W1[(size_t)k * H_ + n]);
    } else {                                // ---- qproj ----
        const int b = blk - 9216;
        __shared__ float xs[H_];
        xs[tid] = dec[b * H_ + tid];
        xs[tid + 256] = dec[b * H_ + tid + 256];
        __syncthreads();
        float a0 = 0.f, a1 = 0.f;
#pragma unroll 8
        for (int h = 0; h < H_; ++h) {
            float x = xs[h];
            a0 += x * W2[(size_t)h * H_ + tid];
            a1 += x * W2[(size_t)h * H_ + tid + 256];
        }
        g_q[b * H_ + tid] = a0;
        g_q[b * H_ + tid + 256] = a1;
    }
}

// ---------------- K1: fp16 mma.sync energy GEMM ----------------
// CTA: 128 rows x 256 cols, K=512 in 8 chunks of 64, 3-stage cp.async pipeline.
// 16 warps, warp grid 4M x 4N, warp tile 32x64. 1 CTA/SM (145KB smem).
#define STG    49152       // per-stage: A 16KB + B 32KB
#define OFF_B  16384
#define DSMEM  (1024 + 3 * STG)   // 148480

__global__ __launch_bounds__(512, 1) void energy_kernel(const float* __restrict__ Vv,
                                                        const int* __restrict__ lens) {
    // grid: b*32 + tile*2 + nc
    const int nc   = blockIdx.x & 1;
    const int tile = (blockIdx.x >> 1) & 15;
    const int b    = blockIdx.x >> 5;
    const int row0 = tile << 7;
    const int n0   = nc << 8;
    if (row0 >= lens[b]) return;

    extern __shared__ char dsm[];
    __shared__ float qs[256], Vs[256], es[128];

    const int tid  = threadIdx.x;
    const int wid  = tid >> 5;
    const int lane = tid & 31;
    const int mbase = (wid & 3) << 5;   // 0..96
    const int nbase = (wid >> 2) << 6;  // 0..192

    const uint32_t dynB = smem_u32(dsm);
    const uint32_t tb   = (dynB + 1023u) & ~1023u;

    if (tid < 256) {
        qs[tid] = g_q[b * H_ + n0 + tid];
        Vs[tid] = Vv[n0 + tid];
    }
    if (tid < 128) es[tid] = 0.f;

    // cp.async slots: A: r = tid>>2 (0..127), q = tid&3 (2x cp16)
    //                 B: rn = tid>>1 (0..255), seg = tid&1 (4x cp16)
    const int ra = tid >> 2, qa = tid & 3;
    const int rb2 = tid >> 1, seg = tid & 1;
    const __half* aSrc = g_encF + ((size_t)b * S_ + row0 + ra) * H_ + qa * 16;
    const __half* bSrc = g_w1tF + ((size_t)(n0 + rb2)) * H_ + seg * 32;
    uint32_t offA[2], offB[4];
#pragma unroll
    for (int j = 0; j < 2; ++j)
        offA[j] = SW128((uint32_t)(ra * 128 + qa * 32 + j * 16));
#pragma unroll
    for (int j = 0; j < 4; ++j)
        offB[j] = SW128((uint32_t)(rb2 * 128 + seg * 64 + j * 16));

    // ldmatrix swizzled bases; kq*32 folds with XOR (bits 5..6), stage adds.
    const int rbl = (((lane & 15) >> 3) << 3) + (lane & 7);
    const int c16 = (lane >> 4) << 4;
    const uint32_t aA0 = tb + SW128((uint32_t)((mbase + rbl) * 128 + c16));
    const uint32_t aA1 = tb + SW128((uint32_t)((mbase + 16 + rbl) * 128 + c16));
    const uint32_t aB0 = tb + OFF_B + SW128((uint32_t)((nbase + rbl) * 128 + c16));
    const uint32_t aB1 = tb + OFF_B + SW128((uint32_t)((nbase + 16 + rbl) * 128 + c16));
    const uint32_t aB2 = tb + OFF_B + SW128((uint32_t)((nbase + 32 + rbl) * 128 + c16));
    const uint32_t aB3 = tb + OFF_B + SW128((uint32_t)((nbase + 48 + rbl) * 128 + c16));

    float acc[2][8][4];
#pragma unroll
    for (int i = 0; i < 2; ++i)
#pragma unroll
        for (int j = 0; j < 8; ++j)
#pragma unroll
            for (int q = 0; q < 4; ++q) acc[i][j][q] = 0.f;

    // prologue: stages 0,1
#pragma unroll
    for (int s = 0; s < 2; ++s) {
        const uint32_t sb = tb + s * STG;
        cp16(sb + offA[0], aSrc + s * 64);
        cp16(sb + offA[1], aSrc + s * 64 + 8);
#pragma unroll
        for (int j = 0; j < 4; ++j)
            cp16(sb + OFF_B + offB[j], bSrc + s * 64 + j * 8);
        cp_commit();
    }

#pragma unroll
    for (int kc = 0; kc < 8; ++kc) {
        if (kc < 7) cp_wait1(); else cp_wait0();
        __syncthreads();

        if (kc < 6) {
            const int ns = kc + 2;
            const uint32_t sb = tb + (ns % 3) * STG;
            cp16(sb + offA[0], aSrc + ns * 64);
            cp16(sb + offA[1], aSrc + ns * 64 + 8);
#pragma unroll
            for (int j = 0; j < 4; ++j)
                cp16(sb + OFF_B + offB[j], bSrc + ns * 64 + j * 8);
            cp_commit();
        }

        const uint32_t so = (kc % 3) * STG;
#pragma unroll
        for (int kq = 0; kq < 4; ++kq) {
            const uint32_t kk = (uint32_t)(kq << 5);
            uint32_t a0[4], a1[4], bf[4][4];
            ldmx4(a0, (aA0 + so) ^ kk);
            ldmx4(a1, (aA1 + so) ^ kk);
            ldmx4(bf[0], (aB0 + so) ^ kk);
            ldmx4(bf[1], (aB1 + so) ^ kk);
            ldmx4(bf[2], (aB2 + so) ^ kk);
            ldmx4(bf[3], (aB3 + so) ^ kk);
#pragma unroll
            for (int t = 0; t < 4; ++t) {
                mma16816(acc[0][t * 2],     a0, bf[t][0], bf[t][2]);
                mma16816(acc[0][t * 2 + 1], a0, bf[t][1], bf[t][3]);
                mma16816(acc[1][t * 2],     a1, bf[t][0], bf[t][2]);
                mma16816(acc[1][t * 2 + 1], a1, bf[t][1], bf[t][3]);
            }
        }
    }
    __syncthreads();

    // ---- epilogue: e[row] += sum_col tanh(d + q[col]) * V[col] ----
    const int gid = lane >> 2, t4 = lane & 3;
#pragma unroll
    for (int mt = 0; mt < 2; ++mt) {
        float s0 = 0.f, s1 = 0.f;
#pragma unroll
        for (int nt = 0; nt < 8; ++nt) {
            int c = nbase + nt * 8 + t4 * 2;
            float q0 = qs[c], q1 = qs[c + 1], v0 = Vs[c], v1 = Vs[c + 1];
            float* d = acc[mt][nt];
            s0 += tanh_fast(d[0] + q0) * v0 + tanh_fast(d[1] + q1) * v1;
            s1 += tanh_fast(d[2] + q0) * v0 + tanh_fast(d[3] + q1) * v1;
        }
        s0 += __shfl_xor_sync(0xffffffffu, s0, 1);
        s0 += __shfl_xor_sync(0xffffffffu, s0, 2);
        s1 += __shfl_xor_sync(0xffffffffu, s1, 1);
        s1 += __shfl_xor_sync(0xffffffffu, s1, 2);
        if (t4 == 0) {
            atomicAdd(&es[mbase + mt * 16 + gid], s0);
            atomicAdd(&es[mbase + mt * 16 + gid + 8], s1);
        }
    }
    __syncthreads();
    if (tid < 128)
        g_ep[nc][b * S_ + row0 + tid] = es[tid];
}

// ---------------- K2: combine partials, mask, stats, zero out ----------------
__global__ __launch_bounds__(256) void stats_kernel(const int* __restrict__ lens,
                                                    float* __restrict__ out) {
    int b = blockIdx.x;
    int tid = threadIdx.x;
    int len = lens[b];
    __shared__ float red[256];

    out[b * H_ + tid] = 0.f;
    out[b * H_ + tid + 256] = 0.f;

    float mx = -3.4e38f;
    for (int s = tid; s < S_; s += 256) {
        int i = b * S_ + s;
        float e = (s < len) ? (g_ep[0][i] + g_ep[1][i]) : NEG_INF_V;
        g_energy[i] = e;
        mx = fmaxf(mx, e);
    }
    red[tid] = mx;
    __syncthreads();
    for (int o = 128; o > 0; o >>= 1) {
        if (tid < o) red[tid] = fmaxf(red[tid], red[tid + o]);
        __syncthreads();
    }
    mx = red[0];
    __syncthreads();

    float sm = 0.f;
    for (int s = tid; s < S_; s += 256) sm += __expf(g_energy[b * S_ + s] - mx);
    red[tid] = sm;
    __syncthreads();
    for (int o = 128; o > 0; o >>= 1) {
        if (tid < o) red[tid] += red[tid + o];
        __syncthreads();
    }
    if (tid == 0) {
        g_mx[b] = mx;
        g_invden[b] = 1.0f / red[0];
    }
}

// ---------------- K3: context = sum_s attn[s] * enc_fp16[b,s,:] ----------------
__global__ __launch_bounds__(256) void context_kernel(const int* __restrict__ lens,
                                                      float* __restrict__ out) {
    const int b     = blockIdx.x >> 5;
    const int chunk = blockIdx.x & 31;
    const int row0  = chunk * 64;
    const int len   = lens[b];
    if (row0 >= len) return;

    __shared__ float ws[64];
    const int tid = threadIdx.x;
    if (tid < 64) {
        float e = g_energy[b * S_ + row0 + tid];
        ws[tid] = __expf(e - g_mx[b]) * g_invden[b];
    }
    __syncthreads();

    const int smax = min(64, len - row0);
    const __half2* base = (const __half2*)(g_encF + ((size_t)b * S_ + row0) * H_) + tid;
    float c0 = 0.f, c1 = 0.f;
#pragma unroll 8
    for (int s = 0; s < smax; ++s) {
        float2 f = __half22float2(base[s * 256]);
        float w = ws[s];
        c0 += w * f.x;
        c1 += w * f.y;
    }
    atomicAdd(&out[b * H_ + tid * 2], c0);
    atomicAdd(&out[b * H_ + tid * 2 + 1], c1);
}

// ---------------- launch ----------------
extern "C" void kernel_launch(void* const* d_in, const int* in_sizes, int n_in,
                              void* d_out, int out_size) {
    const float* dec  = (const float*)d_in[0];
    const float* enc  = (const float*)d_in[1];
    const int*   lens = (const int*)d_in[2];
    const float* W1   = (const float*)d_in[3];
    const float* W2   = (const float*)d_in[4];
    const float* V    = (const float*)d_in[5];
    float* out = (float*)d_out;

    cudaFuncSetAttribute(energy_kernel,
                         cudaFuncAttributeMaxDynamicSharedMemorySize, DSMEM);

    prep_kernel<<<9280, 256>>>(enc, lens, W1, dec, W2);
    energy_kernel<<<B_ * 32, 512, DSMEM>>>(V, lens);
    stats_kernel<<<B_, 256>>>(lens, out);
    context_kernel<<<B_ * (S_ / 64), 256>>>(lens, out);
}